// round 14
// baseline (speedup 1.0000x reference)
#include <cuda_runtime.h>
#include <cuda_fp16.h>
#include <cstdint>

// ============================================================
// out[B,256] = relu(X[B,1024] @ W^T + c),  X = [text | image]
// ONE kernel launch. CTA roles by blockIdx.x:
//   [0,96)    stage-1 GEMMs: X1=Wf1@Wo, X2=Wf2@Wo, Yt=Wv@W_text, Yi=Wv@W_img
//   [96,99)   stage-1 vectors: b1, u_t, u_i
//   [99,163)  stage-2 (spin g_s1): W[:, :512]=X2@Yt, W[:, 512:]=X1@Yi (fp16)
//   163       stage-2 bias: c = X1@u_i + X2@u_t + (Wf1+Wf2)@b1 + b_fuse
//   [164, +1024) fused consumers (spin g_wtot before B loads; g_bias at epi)
// Counters reset by the last CTA to finish (replay-safe).
// ============================================================
#define HDIM 256
#define N_PRE1 99
#define N_WORK 164

// ---------------- device scratch ----------------
__device__ float  g_X1[HDIM * HDIM];
__device__ float  g_X2[HDIM * HDIM];
__device__ float  g_Yt[HDIM * 512];
__device__ float  g_Yi[HDIM * 512];
__device__ __half g_W16[HDIM * 1024];
__device__ float  g_b1[HDIM];
__device__ float  g_ut[HDIM];
__device__ float  g_ui[HDIM];
__device__ float  g_c[HDIM];
// dataflow flags (replay-safe: reset by last CTA)
__device__ int g_s1   = 0;   // stage-1 arrivals, target N_PRE1
__device__ int g_wtot = 0;   // W-tile arrivals,  target 64
__device__ int g_bias = 0;   // bias done flag
__device__ int g_fin  = 0;   // completion counter

// ---------------- PTX helpers ----------------
__device__ __forceinline__ uint32_t smem_u32(const void* p) {
    uint32_t a;
    asm("{ .reg .u64 t; cvta.to.shared.u64 t, %1; cvt.u32.u64 %0, t; }"
        : "=r"(a) : "l"(p));
    return a;
}

#define SW(x) ((x) ^ (((x) >> 3) & 0x70))

#define LDSM_X4(r0, r1, r2, r3, addr) \
    asm volatile("ldmatrix.sync.aligned.m8n8.x4.shared.b16 {%0,%1,%2,%3}, [%4];\n" \
        : "=r"(r0), "=r"(r1), "=r"(r2), "=r"(r3) : "r"(addr))

#define MMA16816(d, a, b0_, b1_) \
    asm volatile("mma.sync.aligned.m16n8k16.row.col.f32.f16.f16.f32 " \
        "{%0,%1,%2,%3}, {%4,%5,%6,%7}, {%8,%9}, {%0,%1,%2,%3};\n" \
        : "+f"((d)[0]), "+f"((d)[1]), "+f"((d)[2]), "+f"((d)[3]) \
        : "r"((a)[0]), "r"((a)[1]), "r"((a)[2]), "r"((a)[3]), "r"(b0_), "r"(b1_))

#define CP_ASYNC16(dst, src) \
    asm volatile("cp.async.cg.shared.global [%0], [%1], 16;\n" :: "r"(dst), "l"(src))
#define CP_COMMIT() asm volatile("cp.async.commit_group;\n")
#define CP_WAIT0()  asm volatile("cp.async.wait_group 0;\n" ::: "memory")

// ============================================================
// Worker GEMM: 64x64 tile, 256 threads, reg-double-buffered (r9)
// ============================================================
template<bool HALF_OUT>
__device__ __forceinline__ void gemm64_body(const float* __restrict__ A, int lda,
                                            const float* __restrict__ B, int ldb,
                                            void* __restrict__ C, int ldc, int K,
                                            int i0, int j0) {
    __shared__ float As[32][72];   // As[k][m] (transposed)
    __shared__ float Bs[32][72];   // Bs[k][n]
    const int t = threadIdx.x;
    const int tx = t & 15, ty = t >> 4;
    float acc[4][4] = {};

    int ar[8], ac[8], br[8], bc[8];
    #pragma unroll
    for (int u = 0; u < 8; u++) {
        int idx = t + u * 256;
        ar[u] = idx >> 5;  ac[u] = idx & 31;   // A: 64 rows x 32 k
        br[u] = idx >> 6;  bc[u] = idx & 63;   // B: 32 k x 64 cols
    }
    float ra[8], rb[8];
    #pragma unroll
    for (int u = 0; u < 8; u++) {
        ra[u] = A[(size_t)(i0 + ar[u]) * lda + ac[u]];
        rb[u] = B[(size_t)br[u] * ldb + j0 + bc[u]];
    }

    for (int k0 = 0; k0 < K; k0 += 32) {
        #pragma unroll
        for (int u = 0; u < 8; u++) {
            As[ac[u]][ar[u]] = ra[u];
            Bs[br[u]][bc[u]] = rb[u];
        }
        __syncthreads();
        if (k0 + 32 < K) {
            #pragma unroll
            for (int u = 0; u < 8; u++) {
                ra[u] = A[(size_t)(i0 + ar[u]) * lda + k0 + 32 + ac[u]];
                rb[u] = B[(size_t)(k0 + 32 + br[u]) * ldb + j0 + bc[u]];
            }
        }
        #pragma unroll
        for (int k = 0; k < 32; k++) {
            float4 a4 = *(const float4*)&As[k][ty * 4];
            float4 b4 = *(const float4*)&Bs[k][tx * 4];
            acc[0][0] += a4.x * b4.x; acc[0][1] += a4.x * b4.y;
            acc[0][2] += a4.x * b4.z; acc[0][3] += a4.x * b4.w;
            acc[1][0] += a4.y * b4.x; acc[1][1] += a4.y * b4.y;
            acc[1][2] += a4.y * b4.z; acc[1][3] += a4.y * b4.w;
            acc[2][0] += a4.z * b4.x; acc[2][1] += a4.z * b4.y;
            acc[2][2] += a4.z * b4.z; acc[2][3] += a4.z * b4.w;
            acc[3][0] += a4.w * b4.x; acc[3][1] += a4.w * b4.y;
            acc[3][2] += a4.w * b4.z; acc[3][3] += a4.w * b4.w;
        }
        __syncthreads();
    }
    #pragma unroll
    for (int r = 0; r < 4; r++)
        #pragma unroll
        for (int c = 0; c < 4; c++) {
            size_t o = (size_t)(i0 + ty * 4 + r) * ldc + j0 + tx * 4 + c;
            if (HALF_OUT) ((__half*)C)[o] = __float2half_rn(acc[r][c]);
            else          ((float*)C)[o]  = acc[r][c];
        }
}

__device__ __forceinline__ float dot256(const float* __restrict__ a,
                                        const float* __restrict__ b) {
    const float4* a4 = (const float4*)a;
    const float4* b4 = (const float4*)b;
    float s = 0.f;
    #pragma unroll 8
    for (int k = 0; k < 64; k++) {
        float4 x = __ldg(&a4[k]), y = __ldg(&b4[k]);
        s += x.x * y.x + x.y * y.y + x.z * y.z + x.w * y.w;
    }
    return s;
}

// ============================================================
// The mega kernel
// ============================================================
#define STAGE 40960                    // 8KB A + 32KB B (fp16)
#define DYNSMEM (1024 + 1024 + 2 * STAGE)

__global__ void __launch_bounds__(256, 2)
mega(const float* __restrict__ text, const float* __restrict__ image,
     float* __restrict__ out,
     const float* __restrict__ Wo, const float* __restrict__ Wv,
     const float* __restrict__ W_fuse,
     const float* __restrict__ W_text, const float* __restrict__ W_img,
     const float* __restrict__ in_proj_b, const float* __restrict__ out_proj_b,
     const float* __restrict__ b_text, const float* __restrict__ b_img,
     const float* __restrict__ b_fuse) {
    const int bid = blockIdx.x;
    const int tid = threadIdx.x;

    if (bid < N_WORK) {
        // =========================== workers ===========================
        if (bid < N_PRE1) {
            // ------- stage 1: input-only work -------
            if (bid < 16) {
                gemm64_body<false>(W_fuse, 512, Wo, 256, g_X1, 256, 256,
                                   (bid >> 2) * 64, (bid & 3) * 64);
            } else if (bid < 32) {
                int r = bid - 16;
                gemm64_body<false>(W_fuse + 256, 512, Wo, 256, g_X2, 256, 256,
                                   (r >> 2) * 64, (r & 3) * 64);
            } else if (bid < 64) {
                int r = bid - 32;
                gemm64_body<false>(Wv, 256, W_text, 512, g_Yt, 512, 256,
                                   (r >> 3) * 64, (r & 7) * 64);
            } else if (bid < 96) {
                int r = bid - 64;
                gemm64_body<false>(Wv, 256, W_img, 512, g_Yi, 512, 256,
                                   (r >> 3) * 64, (r & 7) * 64);
            } else {
                const int i = tid;
                if (bid == 96)
                    g_b1[i] = dot256(Wo + i * HDIM, in_proj_b + 2 * HDIM) + out_proj_b[i];
                else if (bid == 97)
                    g_ut[i] = dot256(Wv + i * HDIM, b_text);
                else
                    g_ui[i] = dot256(Wv + i * HDIM, b_img);
            }
            __threadfence();
            __syncthreads();
            if (tid == 0) atomicAdd(&g_s1, 1);
        } else {
            // ------- stage 2: spin for stage-1 completion -------
            while (*(volatile int*)&g_s1 < N_PRE1) {}
            if (bid < 131) {
                int r = bid - 99;                 // 32 tiles: 4 rows x 8 kcols
                gemm64_body<true>(g_X2, 256, g_Yt, 512, g_W16, 1024, 256,
                                  (r & 3) * 64, (r >> 2) * 64);
            } else if (bid < 163) {
                int r = bid - 131;
                gemm64_body<true>(g_X1, 256, g_Yi, 512, g_W16 + 512, 1024, 256,
                                  (r & 3) * 64, (r >> 2) * 64);
            } else {
                const int i = tid;
                float s = b_fuse[i] + dot256(g_X1 + i * HDIM, g_ui)
                                    + dot256(g_X2 + i * HDIM, g_ut);
                const float4* w1 = (const float4*)(W_fuse + i * 512);
                const float4* w2 = (const float4*)(W_fuse + i * 512 + 256);
                const float4* v1 = (const float4*)g_b1;
                #pragma unroll 8
                for (int k = 0; k < 64; k++) {
                    float4 c1 = __ldg(&w1[k]), c2 = __ldg(&w2[k]), b = v1[k];
                    s += (c1.x + c2.x) * b.x + (c1.y + c2.y) * b.y
                       + (c1.z + c2.z) * b.z + (c1.w + c2.w) * b.w;
                }
                g_c[i] = s;
            }
            __threadfence();
            __syncthreads();
            if (tid == 0) {
                if (bid == 163) atomicExch(&g_bias, 1);
                else            atomicAdd(&g_wtot, 1);
            }
        }
    } else {
        // =========================== consumers ===========================
        extern __shared__ char smem_raw[];
        char* dsm = (char*)(((uintptr_t)smem_raw + 1023) & ~(uintptr_t)1023);
        const uint32_t sb = smem_u32(dsm);
        const int lane = tid & 31;
        const int wid = tid >> 5;          // 0..7
        const int wm = wid & 1;            // 2 m-blocks of 32
        const int wn = wid >> 1;           // 4 n-blocks of 64
        const int mblk = bid - N_WORK;

        const float* srcT = text  + (size_t)mblk * 64 * 512;
        const float* srcI = image + (size_t)mblk * 64 * 512;

        const int a_c4 = tid & 15, a_r0 = tid >> 4;   // A: rows a_r0 + u*16, u<4
        const int b_c16 = tid & 7, b_r0 = tid >> 3;   // B: rows b_r0 + u*32, u<8

        // -------- prologue: stage A chunk 0 while W is being produced --------
        float4 fa[4];
        #pragma unroll
        for (int u = 0; u < 4; u++)
            fa[u] = __ldg((const float4*)(srcT + (size_t)(a_r0 + u * 16) * 512 + a_c4 * 4));
        {
            char* Ab = dsm + 1024;
            #pragma unroll
            for (int u = 0; u < 4; u++) {
                int r = a_r0 + u * 16;
                uint32_t off = SW((uint32_t)(r * 128 + a_c4 * 8));
                __half2 h0 = __floats2half2_rn(fa[u].x, fa[u].y);
                __half2 h1 = __floats2half2_rn(fa[u].z, fa[u].w);
                *(uint2*)(Ab + off) = make_uint2(*(uint32_t*)&h0, *(uint32_t*)&h1);
            }
        }
        // wait for ALL W tiles (producers fence before arriving)
        while (*(volatile int*)&g_wtot < 64) {}
        {
            uint32_t Bb = sb + 1024 + 8192;
            #pragma unroll
            for (int u = 0; u < 8; u++) {
                int r = b_r0 + u * 32;
                uint32_t dst = Bb + SW((uint32_t)(r * 128 + b_c16 * 16));
                CP_ASYNC16(dst, g_W16 + (size_t)r * 1024 + b_c16 * 8);
            }
            CP_COMMIT();
        }
        CP_WAIT0();
        __syncthreads();

        float acc[2][8][4] = {};

        const uint32_t xorv  = (uint32_t)((lane & 7) << 4);
        const int      rl    = lane & 15;
        const uint32_t khalf = (uint32_t)(((lane >> 4) & 1) * 16);

        #pragma unroll 1
        for (int kc = 0; kc < 16; kc++) {
            const int cur = kc & 1;
            const int nxt = cur ^ 1;

            if (kc < 15) {
                const int kn = kc + 1;
                const float* src = (kn < 8) ? srcT : srcI;
                const int kl = (kn & 7) * 64;
                #pragma unroll
                for (int u = 0; u < 4; u++)
                    fa[u] = __ldg((const float4*)(src + (size_t)(a_r0 + u * 16) * 512 + kl + a_c4 * 4));
                uint32_t Bb = sb + 1024 + nxt * STAGE + 8192;
                #pragma unroll
                for (int u = 0; u < 8; u++) {
                    int r = b_r0 + u * 32;
                    uint32_t dst = Bb + SW((uint32_t)(r * 128 + b_c16 * 16));
                    CP_ASYNC16(dst, g_W16 + (size_t)r * 1024 + kn * 64 + b_c16 * 8);
                }
                CP_COMMIT();
            }

            // ---- compute on cur, fragment-pipelined ----
            const uint32_t Ab = sb + 1024 + cur * STAGE;
            const uint32_t Bb = Ab + 8192;
            uint32_t af[2][2][4];
            uint32_t bf[2][4];

            #pragma unroll
            for (int im = 0; im < 2; im++) {
                uint32_t addr = (Ab + (uint32_t)((wm * 32 + im * 16 + rl) * 128) + khalf) ^ xorv;
                LDSM_X4(af[0][im][0], af[0][im][1], af[0][im][2], af[0][im][3], addr);
            }
            {
                uint32_t addr = (Bb + (uint32_t)((wn * 64 + rl) * 128) + khalf) ^ xorv;
                LDSM_X4(bf[0][0], bf[0][1], bf[0][2], bf[0][3], addr);
            }

            #pragma unroll
            for (int ks = 0; ks < 4; ks++) {
                const int cb = ks & 1;
                #pragma unroll
                for (int in_ = 0; in_ < 4; in_++) {
                    const int bc = in_ & 1, bn = bc ^ 1;
                    if (in_ < 3) {
                        uint32_t addr = (Bb + (uint32_t)((wn * 64 + (in_ + 1) * 16 + rl) * 128)
                                            + (uint32_t)(ks * 32) + khalf) ^ xorv;
                        LDSM_X4(bf[bn][0], bf[bn][1], bf[bn][2], bf[bn][3], addr);
                    } else if (ks < 3) {
                        #pragma unroll
                        for (int im = 0; im < 2; im++) {
                            uint32_t addr = (Ab + (uint32_t)((wm * 32 + im * 16 + rl) * 128)
                                                + (uint32_t)((ks + 1) * 32) + khalf) ^ xorv;
                            LDSM_X4(af[cb ^ 1][im][0], af[cb ^ 1][im][1],
                                    af[cb ^ 1][im][2], af[cb ^ 1][im][3], addr);
                        }
                        uint32_t addr = (Bb + (uint32_t)((wn * 64 + rl) * 128)
                                            + (uint32_t)((ks + 1) * 32) + khalf) ^ xorv;
                        LDSM_X4(bf[bn][0], bf[bn][1], bf[bn][2], bf[bn][3], addr);
                    }
                    #pragma unroll
                    for (int im = 0; im < 2; im++) {
                        MMA16816(acc[im][2 * in_],     af[cb][im], bf[bc][0], bf[bc][2]);
                        MMA16816(acc[im][2 * in_ + 1], af[cb][im], bf[bc][1], bf[bc][3]);
                    }
                }
            }

            if (kc < 15) {
                char* Abn = dsm + 1024 + nxt * STAGE;
                #pragma unroll
                for (int u = 0; u < 4; u++) {
                    int r = a_r0 + u * 16;
                    uint32_t off = SW((uint32_t)(r * 128 + a_c4 * 8));
                    __half2 h0 = __floats2half2_rn(fa[u].x, fa[u].y);
                    __half2 h1 = __floats2half2_rn(fa[u].z, fa[u].w);
                    *(uint2*)(Abn + off) = make_uint2(*(uint32_t*)&h0, *(uint32_t*)&h1);
                }
                CP_WAIT0();
            }
            __syncthreads();
        }

        // -------- epilogue: wait bias, + bias, relu, store --------
        while (*(volatile int*)&g_bias == 0) {}
        float* bias_s = (float*)dsm;
        bias_s[tid] = g_c[tid];
        __syncthreads();

        const int g = lane >> 2;
        const int cpair = (lane & 3) * 2;
        #pragma unroll
        for (int im = 0; im < 2; im++) {
            int m0 = mblk * 64 + wm * 32 + im * 16 + g;
            #pragma unroll
            for (int j = 0; j < 8; j++) {
                int n = wn * 64 + j * 8 + cpair;
                float bv0 = bias_s[n], bv1 = bias_s[n + 1];
                float2 v0 = make_float2(fmaxf(acc[im][j][0] + bv0, 0.f),
                                        fmaxf(acc[im][j][1] + bv1, 0.f));
                float2 v1 = make_float2(fmaxf(acc[im][j][2] + bv0, 0.f),
                                        fmaxf(acc[im][j][3] + bv1, 0.f));
                *(float2*)(out + (size_t)m0 * 256 + n)       = v0;
                *(float2*)(out + (size_t)(m0 + 8) * 256 + n) = v1;
            }
        }
    }

    // ---------------- common finish: replay-safe flag reset ----------------
    __threadfence();
    __syncthreads();
    if (tid == 0) {
        int v = atomicAdd(&g_fin, 1);
        if (v == (int)gridDim.x - 1) {
            g_s1 = 0;
            g_wtot = 0;
            g_bias = 0;
            g_fin = 0;
            __threadfence();
        }
    }
}

// ============================================================
// kernel_launch — ONE launch
// ============================================================
extern "C" void kernel_launch(void* const* d_in, const int* in_sizes, int n_in,
                              void* d_out, int out_size) {
    const float* text       = (const float*)d_in[0];
    const float* image      = (const float*)d_in[1];
    const float* W_text     = (const float*)d_in[2];
    const float* b_text     = (const float*)d_in[3];
    const float* W_img      = (const float*)d_in[4];
    const float* b_img      = (const float*)d_in[5];
    const float* in_proj_w  = (const float*)d_in[6];
    const float* in_proj_b  = (const float*)d_in[7];
    const float* out_proj_w = (const float*)d_in[8];
    const float* out_proj_b = (const float*)d_in[9];
    const float* W_fuse     = (const float*)d_in[10];
    const float* b_fuse     = (const float*)d_in[11];
    const int batch = in_sizes[0] / 512;

    cudaFuncSetAttribute(mega, cudaFuncAttributeMaxDynamicSharedMemorySize, DYNSMEM);
    mega<<<N_WORK + batch / 64, 256, DYNSMEM>>>(
        text, image, (float*)d_out,
        out_proj_w, in_proj_w + 512 * 256, W_fuse, W_text, W_img,
        in_proj_b, out_proj_b, b_text, b_img, b_fuse);
}

// round 15
// speedup vs baseline: 1.2314x; 1.2314x over previous
#include <cuda_runtime.h>
#include <cuda_fp16.h>
#include <cstdint>

// ============================================================
// out[B,256] = relu(X[B,1024] @ W^T + c),  X = [text | image]
// ONE kernel launch. CTA roles by blockIdx.x:
//   [0,96)    stage-1 GEMMs: X1=Wf1@Wo, X2=Wf2@Wo, Yt=Wv@W_text, Yi=Wv@W_img
//   [96,99)   stage-1 vectors: b1, u_t, u_i
//   [99,163)  stage-2 (spin g_s1): W[:, :512]=X2@Yt, W[:, 512:]=X1@Yi (fp16)
//   163       stage-2 bias: c = X1@u_i + X2@u_t + (Wf1+Wf2)@b1 + b_fuse
//   [164, +1024) fused consumers (spin g_wtot before B loads; g_bias at epi)
// ALL smem is dynamic (workers carve As/Bs from it) so consumers
// keep 2 CTAs/SM. Spins use __nanosleep. Flags reset by last CTA.
// ============================================================
#define HDIM 256
#define N_PRE1 99
#define N_WORK 164

// ---------------- device scratch ----------------
__device__ float  g_X1[HDIM * HDIM];
__device__ float  g_X2[HDIM * HDIM];
__device__ float  g_Yt[HDIM * 512];
__device__ float  g_Yi[HDIM * 512];
__device__ __half g_W16[HDIM * 1024];
__device__ float  g_b1[HDIM];
__device__ float  g_ut[HDIM];
__device__ float  g_ui[HDIM];
__device__ float  g_c[HDIM];
// dataflow flags (replay-safe: reset by last CTA)
__device__ int g_s1   = 0;   // stage-1 arrivals, target N_PRE1
__device__ int g_wtot = 0;   // W-tile arrivals,  target 64
__device__ int g_bias = 0;   // bias done flag
__device__ int g_fin  = 0;   // completion counter

// ---------------- PTX helpers ----------------
__device__ __forceinline__ uint32_t smem_u32(const void* p) {
    uint32_t a;
    asm("{ .reg .u64 t; cvta.to.shared.u64 t, %1; cvt.u32.u64 %0, t; }"
        : "=r"(a) : "l"(p));
    return a;
}

#define SW(x) ((x) ^ (((x) >> 3) & 0x70))

#define LDSM_X4(r0, r1, r2, r3, addr) \
    asm volatile("ldmatrix.sync.aligned.m8n8.x4.shared.b16 {%0,%1,%2,%3}, [%4];\n" \
        : "=r"(r0), "=r"(r1), "=r"(r2), "=r"(r3) : "r"(addr))

#define MMA16816(d, a, b0_, b1_) \
    asm volatile("mma.sync.aligned.m16n8k16.row.col.f32.f16.f16.f32 " \
        "{%0,%1,%2,%3}, {%4,%5,%6,%7}, {%8,%9}, {%0,%1,%2,%3};\n" \
        : "+f"((d)[0]), "+f"((d)[1]), "+f"((d)[2]), "+f"((d)[3]) \
        : "r"((a)[0]), "r"((a)[1]), "r"((a)[2]), "r"((a)[3]), "r"(b0_), "r"(b1_))

#define CP_ASYNC16(dst, src) \
    asm volatile("cp.async.cg.shared.global [%0], [%1], 16;\n" :: "r"(dst), "l"(src))
#define CP_COMMIT() asm volatile("cp.async.commit_group;\n")
#define CP_WAIT0()  asm volatile("cp.async.wait_group 0;\n" ::: "memory")

__device__ __forceinline__ void spin_wait(volatile int* flag, int target) {
    while (*flag < target) { __nanosleep(200); }
}

// ============================================================
// Worker GEMM: 64x64 tile, 256 threads, reg-double-buffered,
// smem provided by caller (dynamic).
// ============================================================
template<bool HALF_OUT>
__device__ __forceinline__ void gemm64_body(float* __restrict__ As,   // [32][72]
                                            float* __restrict__ Bs,   // [32][72]
                                            const float* __restrict__ A, int lda,
                                            const float* __restrict__ B, int ldb,
                                            void* __restrict__ C, int ldc, int K,
                                            int i0, int j0) {
    const int t = threadIdx.x;
    const int tx = t & 15, ty = t >> 4;
    float acc[4][4] = {};

    int ar[8], ac[8], br[8], bc[8];
    #pragma unroll
    for (int u = 0; u < 8; u++) {
        int idx = t + u * 256;
        ar[u] = idx >> 5;  ac[u] = idx & 31;   // A: 64 rows x 32 k
        br[u] = idx >> 6;  bc[u] = idx & 63;   // B: 32 k x 64 cols
    }
    float ra[8], rb[8];
    #pragma unroll
    for (int u = 0; u < 8; u++) {
        ra[u] = A[(size_t)(i0 + ar[u]) * lda + ac[u]];
        rb[u] = B[(size_t)br[u] * ldb + j0 + bc[u]];
    }

    for (int k0 = 0; k0 < K; k0 += 32) {
        #pragma unroll
        for (int u = 0; u < 8; u++) {
            As[ac[u] * 72 + ar[u]] = ra[u];
            Bs[br[u] * 72 + bc[u]] = rb[u];
        }
        __syncthreads();
        if (k0 + 32 < K) {
            #pragma unroll
            for (int u = 0; u < 8; u++) {
                ra[u] = A[(size_t)(i0 + ar[u]) * lda + k0 + 32 + ac[u]];
                rb[u] = B[(size_t)(k0 + 32 + br[u]) * ldb + j0 + bc[u]];
            }
        }
        #pragma unroll
        for (int k = 0; k < 32; k++) {
            float4 a4 = *(const float4*)&As[k * 72 + ty * 4];
            float4 b4 = *(const float4*)&Bs[k * 72 + tx * 4];
            acc[0][0] += a4.x * b4.x; acc[0][1] += a4.x * b4.y;
            acc[0][2] += a4.x * b4.z; acc[0][3] += a4.x * b4.w;
            acc[1][0] += a4.y * b4.x; acc[1][1] += a4.y * b4.y;
            acc[1][2] += a4.y * b4.z; acc[1][3] += a4.y * b4.w;
            acc[2][0] += a4.z * b4.x; acc[2][1] += a4.z * b4.y;
            acc[2][2] += a4.z * b4.z; acc[2][3] += a4.z * b4.w;
            acc[3][0] += a4.w * b4.x; acc[3][1] += a4.w * b4.y;
            acc[3][2] += a4.w * b4.z; acc[3][3] += a4.w * b4.w;
        }
        __syncthreads();
    }
    #pragma unroll
    for (int r = 0; r < 4; r++)
        #pragma unroll
        for (int c = 0; c < 4; c++) {
            size_t o = (size_t)(i0 + ty * 4 + r) * ldc + j0 + tx * 4 + c;
            if (HALF_OUT) ((__half*)C)[o] = __float2half_rn(acc[r][c]);
            else          ((float*)C)[o]  = acc[r][c];
        }
}

__device__ __forceinline__ float dot256(const float* __restrict__ a,
                                        const float* __restrict__ b) {
    const float4* a4 = (const float4*)a;
    const float4* b4 = (const float4*)b;
    float s = 0.f;
    #pragma unroll 8
    for (int k = 0; k < 64; k++) {
        float4 x = __ldg(&a4[k]), y = __ldg(&b4[k]);
        s += x.x * y.x + x.y * y.y + x.z * y.z + x.w * y.w;
    }
    return s;
}

// ============================================================
// The mega kernel (one launch)
// ============================================================
#define STAGE 40960                    // 8KB A + 32KB B (fp16)
#define DYNSMEM (1024 + 1024 + 2 * STAGE)

__global__ void __launch_bounds__(256, 2)
mega(const float* __restrict__ text, const float* __restrict__ image,
     float* __restrict__ out,
     const float* __restrict__ Wo, const float* __restrict__ Wv,
     const float* __restrict__ W_fuse,
     const float* __restrict__ W_text, const float* __restrict__ W_img,
     const float* __restrict__ in_proj_b, const float* __restrict__ out_proj_b,
     const float* __restrict__ b_text, const float* __restrict__ b_img,
     const float* __restrict__ b_fuse) {
    extern __shared__ char smem_raw[];
    char* dsm = (char*)(((uintptr_t)smem_raw + 1023) & ~(uintptr_t)1023);
    const int bid = blockIdx.x;
    const int tid = threadIdx.x;

    if (bid < N_WORK) {
        // =========================== workers ===========================
        float* As = (float*)dsm;             // 32*72 floats
        float* Bs = As + 32 * 72;
        if (bid < N_PRE1) {
            // ------- stage 1: input-only work -------
            if (bid < 16) {
                gemm64_body<false>(As, Bs, W_fuse, 512, Wo, 256, g_X1, 256, 256,
                                   (bid >> 2) * 64, (bid & 3) * 64);
            } else if (bid < 32) {
                int r = bid - 16;
                gemm64_body<false>(As, Bs, W_fuse + 256, 512, Wo, 256, g_X2, 256, 256,
                                   (r >> 2) * 64, (r & 3) * 64);
            } else if (bid < 64) {
                int r = bid - 32;
                gemm64_body<false>(As, Bs, Wv, 256, W_text, 512, g_Yt, 512, 256,
                                   (r >> 3) * 64, (r & 7) * 64);
            } else if (bid < 96) {
                int r = bid - 64;
                gemm64_body<false>(As, Bs, Wv, 256, W_img, 512, g_Yi, 512, 256,
                                   (r >> 3) * 64, (r & 7) * 64);
            } else {
                const int i = tid;
                if (bid == 96)
                    g_b1[i] = dot256(Wo + i * HDIM, in_proj_b + 2 * HDIM) + out_proj_b[i];
                else if (bid == 97)
                    g_ut[i] = dot256(Wv + i * HDIM, b_text);
                else
                    g_ui[i] = dot256(Wv + i * HDIM, b_img);
            }
            __threadfence();
            __syncthreads();
            if (tid == 0) atomicAdd(&g_s1, 1);
        } else {
            // ------- stage 2: spin for stage-1 completion -------
            if (tid == 0) spin_wait(&g_s1, N_PRE1);
            __syncthreads();
            __threadfence();
            if (bid < 131) {
                int r = bid - 99;                 // 32 tiles: 4 rows x 8 kcols
                gemm64_body<true>(As, Bs, g_X2, 256, g_Yt, 512, g_W16, 1024, 256,
                                  (r & 3) * 64, (r >> 2) * 64);
            } else if (bid < 163) {
                int r = bid - 131;
                gemm64_body<true>(As, Bs, g_X1, 256, g_Yi, 512, g_W16 + 512, 1024, 256,
                                  (r & 3) * 64, (r >> 2) * 64);
            } else {
                const int i = tid;
                float s = b_fuse[i] + dot256(g_X1 + i * HDIM, g_ui)
                                    + dot256(g_X2 + i * HDIM, g_ut);
                const float4* w1 = (const float4*)(W_fuse + i * 512);
                const float4* w2 = (const float4*)(W_fuse + i * 512 + 256);
                const float4* v1 = (const float4*)g_b1;
                #pragma unroll 8
                for (int k = 0; k < 64; k++) {
                    float4 c1 = __ldg(&w1[k]), c2 = __ldg(&w2[k]), b = v1[k];
                    s += (c1.x + c2.x) * b.x + (c1.y + c2.y) * b.y
                       + (c1.z + c2.z) * b.z + (c1.w + c2.w) * b.w;
                }
                g_c[i] = s;
            }
            __threadfence();
            __syncthreads();
            if (tid == 0) {
                if (bid == 163) atomicExch(&g_bias, 1);
                else            atomicAdd(&g_wtot, 1);
            }
        }
    } else {
        // =========================== consumers ===========================
        const uint32_t sb = smem_u32(dsm);
        const int lane = tid & 31;
        const int wid = tid >> 5;          // 0..7
        const int wm = wid & 1;            // 2 m-blocks of 32
        const int wn = wid >> 1;           // 4 n-blocks of 64
        const int mblk = bid - N_WORK;

        const float* srcT = text  + (size_t)mblk * 64 * 512;
        const float* srcI = image + (size_t)mblk * 64 * 512;

        const int a_c4 = tid & 15, a_r0 = tid >> 4;   // A: rows a_r0 + u*16, u<4
        const int b_c16 = tid & 7, b_r0 = tid >> 3;   // B: rows b_r0 + u*32, u<8

        // -------- prologue: stage A chunk 0 while W is being produced --------
        float4 fa[4];
        #pragma unroll
        for (int u = 0; u < 4; u++)
            fa[u] = __ldg((const float4*)(srcT + (size_t)(a_r0 + u * 16) * 512 + a_c4 * 4));
        {
            char* Ab = dsm + 1024;
            #pragma unroll
            for (int u = 0; u < 4; u++) {
                int r = a_r0 + u * 16;
                uint32_t off = SW((uint32_t)(r * 128 + a_c4 * 8));
                __half2 h0 = __floats2half2_rn(fa[u].x, fa[u].y);
                __half2 h1 = __floats2half2_rn(fa[u].z, fa[u].w);
                *(uint2*)(Ab + off) = make_uint2(*(uint32_t*)&h0, *(uint32_t*)&h1);
            }
        }
        // wait for ALL W tiles (producers fence before arriving)
        if (tid == 0) spin_wait(&g_wtot, 64);
        __syncthreads();
        {
            uint32_t Bb = sb + 1024 + 8192;
            #pragma unroll
            for (int u = 0; u < 8; u++) {
                int r = b_r0 + u * 32;
                uint32_t dst = Bb + SW((uint32_t)(r * 128 + b_c16 * 16));
                CP_ASYNC16(dst, g_W16 + (size_t)r * 1024 + b_c16 * 8);
            }
            CP_COMMIT();
        }
        CP_WAIT0();
        __syncthreads();

        float acc[2][8][4] = {};

        const uint32_t xorv  = (uint32_t)((lane & 7) << 4);
        const int      rl    = lane & 15;
        const uint32_t khalf = (uint32_t)(((lane >> 4) & 1) * 16);

        #pragma unroll 1
        for (int kc = 0; kc < 16; kc++) {
            const int cur = kc & 1;
            const int nxt = cur ^ 1;

            if (kc < 15) {
                const int kn = kc + 1;
                const float* src = (kn < 8) ? srcT : srcI;
                const int kl = (kn & 7) * 64;
                #pragma unroll
                for (int u = 0; u < 4; u++)
                    fa[u] = __ldg((const float4*)(src + (size_t)(a_r0 + u * 16) * 512 + kl + a_c4 * 4));
                uint32_t Bb = sb + 1024 + nxt * STAGE + 8192;
                #pragma unroll
                for (int u = 0; u < 8; u++) {
                    int r = b_r0 + u * 32;
                    uint32_t dst = Bb + SW((uint32_t)(r * 128 + b_c16 * 16));
                    CP_ASYNC16(dst, g_W16 + (size_t)r * 1024 + kn * 64 + b_c16 * 8);
                }
                CP_COMMIT();
            }

            // ---- compute on cur, fragment-pipelined ----
            const uint32_t Ab = sb + 1024 + cur * STAGE;
            const uint32_t Bb = Ab + 8192;
            uint32_t af[2][2][4];
            uint32_t bf[2][4];

            #pragma unroll
            for (int im = 0; im < 2; im++) {
                uint32_t addr = (Ab + (uint32_t)((wm * 32 + im * 16 + rl) * 128) + khalf) ^ xorv;
                LDSM_X4(af[0][im][0], af[0][im][1], af[0][im][2], af[0][im][3], addr);
            }
            {
                uint32_t addr = (Bb + (uint32_t)((wn * 64 + rl) * 128) + khalf) ^ xorv;
                LDSM_X4(bf[0][0], bf[0][1], bf[0][2], bf[0][3], addr);
            }

            #pragma unroll
            for (int ks = 0; ks < 4; ks++) {
                const int cb = ks & 1;
                #pragma unroll
                for (int in_ = 0; in_ < 4; in_++) {
                    const int bc = in_ & 1, bn = bc ^ 1;
                    if (in_ < 3) {
                        uint32_t addr = (Bb + (uint32_t)((wn * 64 + (in_ + 1) * 16 + rl) * 128)
                                            + (uint32_t)(ks * 32) + khalf) ^ xorv;
                        LDSM_X4(bf[bn][0], bf[bn][1], bf[bn][2], bf[bn][3], addr);
                    } else if (ks < 3) {
                        #pragma unroll
                        for (int im = 0; im < 2; im++) {
                            uint32_t addr = (Ab + (uint32_t)((wm * 32 + im * 16 + rl) * 128)
                                                + (uint32_t)((ks + 1) * 32) + khalf) ^ xorv;
                            LDSM_X4(af[cb ^ 1][im][0], af[cb ^ 1][im][1],
                                    af[cb ^ 1][im][2], af[cb ^ 1][im][3], addr);
                        }
                        uint32_t addr = (Bb + (uint32_t)((wn * 64 + rl) * 128)
                                            + (uint32_t)((ks + 1) * 32) + khalf) ^ xorv;
                        LDSM_X4(bf[bn][0], bf[bn][1], bf[bn][2], bf[bn][3], addr);
                    }
                    #pragma unroll
                    for (int im = 0; im < 2; im++) {
                        MMA16816(acc[im][2 * in_],     af[cb][im], bf[bc][0], bf[bc][2]);
                        MMA16816(acc[im][2 * in_ + 1], af[cb][im], bf[bc][1], bf[bc][3]);
                    }
                }
            }

            if (kc < 15) {
                char* Abn = dsm + 1024 + nxt * STAGE;
                #pragma unroll
                for (int u = 0; u < 4; u++) {
                    int r = a_r0 + u * 16;
                    uint32_t off = SW((uint32_t)(r * 128 + a_c4 * 8));
                    __half2 h0 = __floats2half2_rn(fa[u].x, fa[u].y);
                    __half2 h1 = __floats2half2_rn(fa[u].z, fa[u].w);
                    *(uint2*)(Abn + off) = make_uint2(*(uint32_t*)&h0, *(uint32_t*)&h1);
                }
                CP_WAIT0();
            }
            __syncthreads();
        }

        // -------- epilogue: wait bias, + bias, relu, store --------
        if (tid == 0) spin_wait(&g_bias, 1);
        __syncthreads();
        float* bias_s = (float*)dsm;
        bias_s[tid] = g_c[tid];
        __syncthreads();

        const int g = lane >> 2;
        const int cpair = (lane & 3) * 2;
        #pragma unroll
        for (int im = 0; im < 2; im++) {
            int m0 = mblk * 64 + wm * 32 + im * 16 + g;
            #pragma unroll
            for (int j = 0; j < 8; j++) {
                int n = wn * 64 + j * 8 + cpair;
                float bv0 = bias_s[n], bv1 = bias_s[n + 1];
                float2 v0 = make_float2(fmaxf(acc[im][j][0] + bv0, 0.f),
                                        fmaxf(acc[im][j][1] + bv1, 0.f));
                float2 v1 = make_float2(fmaxf(acc[im][j][2] + bv0, 0.f),
                                        fmaxf(acc[im][j][3] + bv1, 0.f));
                *(float2*)(out + (size_t)m0 * 256 + n)       = v0;
                *(float2*)(out + (size_t)(m0 + 8) * 256 + n) = v1;
            }
        }
    }

    // ---------------- common finish: replay-safe flag reset ----------------
    __threadfence();
    __syncthreads();
    if (tid == 0) {
        int v = atomicAdd(&g_fin, 1);
        if (v == (int)gridDim.x - 1) {
            g_s1 = 0;
            g_wtot = 0;
            g_bias = 0;
            g_fin = 0;
            __threadfence();
        }
    }
}

// ============================================================
// kernel_launch — ONE launch
// ============================================================
extern "C" void kernel_launch(void* const* d_in, const int* in_sizes, int n_in,
                              void* d_out, int out_size) {
    const float* text       = (const float*)d_in[0];
    const float* image      = (const float*)d_in[1];
    const float* W_text     = (const float*)d_in[2];
    const float* b_text     = (const float*)d_in[3];
    const float* W_img      = (const float*)d_in[4];
    const float* b_img      = (const float*)d_in[5];
    const float* in_proj_w  = (const float*)d_in[6];
    const float* in_proj_b  = (const float*)d_in[7];
    const float* out_proj_w = (const float*)d_in[8];
    const float* out_proj_b = (const float*)d_in[9];
    const float* W_fuse     = (const float*)d_in[10];
    const float* b_fuse     = (const float*)d_in[11];
    const int batch = in_sizes[0] / 512;

    cudaFuncSetAttribute(mega, cudaFuncAttributeMaxDynamicSharedMemorySize, DYNSMEM);
    mega<<<N_WORK + batch / 64, 256, DYNSMEM>>>(
        text, image, (float*)d_out,
        out_proj_w, in_proj_w + 512 * 256, W_fuse, W_text, W_img,
        in_proj_b, out_proj_b, b_text, b_img, b_fuse);
}